// round 10
// baseline (speedup 1.0000x reference)
#include <cuda_runtime.h>
#include <cstdint>

// PScan: Y_t = A_t @ Y_{t-1} + X_t  (Y_0 = X_0), per (b,c) chain.
// Shapes: A,X,Y = [B=4, L=2048, C=16, 16, 16] fp32, row-major.
// Chunked scan (TT=32), cp.async staging, f32x2 FFMA, split-k half-warps.
// Phase3: depth-6 cp.async ring + direct streaming STG.32.

#define BB 4
#define LL 2048
#define CC 16
#define TT 32
#define NCHUNK (LL / TT)            // 64
#define CHAINS (BB * CC)            // 64
#define TOTCHUNK (CHAINS * NCHUNK)  // 4096
#define STEP_STRIDE (CC * 256)

typedef unsigned long long u64;

__device__ float g_Pagg[TOTCHUNK * 256];
__device__ float g_Zagg[TOTCHUNK * 256];
__device__ float g_carry[TOTCHUNK * 256];

__device__ __forceinline__ u64 ffma2(u64 a, u64 b, u64 c) {
    u64 d;
    asm("fma.rn.f32x2 %0, %1, %2, %3;" : "=l"(d) : "l"(a), "l"(b), "l"(c));
    return d;
}
__device__ __forceinline__ u64 add2(u64 a, u64 b) {
    u64 d;
    asm("add.rn.f32x2 %0, %1, %2;" : "=l"(d) : "l"(a), "l"(b));
    return d;
}
__device__ __forceinline__ u64 pack2(float lo, float hi) {
    u64 d;
    asm("mov.b64 %0, {%1, %2};" : "=l"(d) : "f"(lo), "f"(hi));
    return d;
}
__device__ __forceinline__ void unpack2(u64 v, float& lo, float& hi) {
    asm("mov.b64 {%0, %1}, %2;" : "=f"(lo), "=f"(hi) : "l"(v));
}

__device__ __forceinline__ void cp16(float* smem_dst, const float* gsrc) {
    uint32_t s = (uint32_t)__cvta_generic_to_shared(smem_dst);
    asm volatile("cp.async.ca.shared.global [%0], [%1], 16;\n" :: "r"(s), "l"(gsrc));
}
#define CP_COMMIT() asm volatile("cp.async.commit_group;\n" ::: "memory")
#define CP_WAIT0()  asm volatile("cp.async.wait_group 0;\n" ::: "memory")
#define CP_WAIT1()  asm volatile("cp.async.wait_group 1;\n" ::: "memory")
#define CP_WAIT5()  asm volatile("cp.async.wait_group 5;\n" ::: "memory")
#define CP_WAIT7()  asm volatile("cp.async.wait_group 7;\n" ::: "memory")

// partial dot of one A-row k-half (a0,a1 = 4 f32x2) with packed state st[4]
__device__ __forceinline__ float dot8(ulonglong2 a0, ulonglong2 a1, const u64* st)
{
    u64 acc0 = ffma2(a0.x, st[0], 0ull);
    u64 acc1 = ffma2(a0.y, st[1], 0ull);
    acc0 = ffma2(a1.x, st[2], acc0);
    acc1 = ffma2(a1.y, st[3], acc1);
    float lo, hi;
    unpack2(add2(acc0, acc1), lo, hi);
    return lo + hi;
}

// ============================================================================
// Phase 1 (R4/R7-proven): chunk aggregates, depth-2 double buffer, split-k.
// ============================================================================
__global__ void __launch_bounds__(64) phase1_kernel(
    const float* __restrict__ A, const float* __restrict__ X)
{
    __shared__ __align__(16) float sm[2][2][512];  // [warp][buf][A:256|X:256]

    const int wid  = threadIdx.x >> 5;
    const int lane = threadIdx.x & 31;
    const int w    = blockIdx.x * 2 + wid;
    const int chain = w / NCHUNK;
    const int chunk = w % NCHUNK;
    const int b = chain >> 4;
    const int c = chain & 15;
    const int t0 = chunk * TT;
    const int j = lane & 15;
    const int h = lane >> 4;

    const int base0 = ((b * LL + t0) * CC + c) * 256;
    const float* src = (h == 0 ? A : X) + base0 + j * 4;
    float* dst0 = sm[wid][0] + (h == 0 ? 0 : 256) + j * 4;
    float* dst1 = sm[wid][1] + (h == 0 ? 0 : 256) + j * 4;

#pragma unroll
    for (int q = 0; q < 4; q++) cp16(dst0 + q * 64, src + q * 64);
    CP_COMMIT();

    u64 zst[4], pst[4];
#pragma unroll
    for (int mm = 0; mm < 4; mm++) {
        zst[mm] = 0ull;
        int k0 = 8 * h + 2 * mm;
        pst[mm] = pack2(j == k0 ? 1.f : 0.f, j == k0 + 1 ? 1.f : 0.f);
    }

#pragma unroll 1
    for (int t = 0; t < TT; t++) {
        if (t + 1 < TT) {
            const float* s2 = src + (t + 1) * STEP_STRIDE;
            float* dn = (t & 1) ? dst0 : dst1;
#pragma unroll
            for (int q = 0; q < 4; q++) cp16(dn + q * 64, s2 + q * 64);
            CP_COMMIT();
            CP_WAIT1();
        } else {
            CP_WAIT0();
        }
        __syncwarp();

        const float* As = sm[wid][t & 1];
        const float* Xs = As + 256;
        const float* Ah = As + h * 8;

        float zpL[8], zpH[8], ppL[8], ppH[8];
#pragma unroll
        for (int r = 0; r < 8; r++) {
            ulonglong2 a0 = *(const ulonglong2*)(Ah + r * 16);
            ulonglong2 a1 = *(const ulonglong2*)(Ah + r * 16 + 4);
            zpL[r] = dot8(a0, a1, zst);
            ppL[r] = dot8(a0, a1, pst);
            ulonglong2 b0 = *(const ulonglong2*)(Ah + (8 + r) * 16);
            ulonglong2 b1 = *(const ulonglong2*)(Ah + (8 + r) * 16 + 4);
            zpH[r] = dot8(b0, b1, zst);
            ppH[r] = dot8(b0, b1, pst);
        }

        float zn[8], pn[8];
#pragma unroll
        for (int r = 0; r < 8; r++) {
            float zsend = h ? zpL[r] : zpH[r];
            float zrecv = __shfl_xor_sync(0xffffffffu, zsend, 16);
            float zown  = h ? zpH[r] : zpL[r];
            float xv = Xs[(8 * h + r) * 16 + j];
            zn[r] = zown + zrecv + xv;

            float psend = h ? ppL[r] : ppH[r];
            float precv = __shfl_xor_sync(0xffffffffu, psend, 16);
            float pown  = h ? ppH[r] : ppL[r];
            pn[r] = pown + precv;
        }
#pragma unroll
        for (int mm = 0; mm < 4; mm++) {
            zst[mm] = pack2(zn[2 * mm], zn[2 * mm + 1]);
            pst[mm] = pack2(pn[2 * mm], pn[2 * mm + 1]);
        }
        __syncwarp();
    }

    const int ab = w * 256;
#pragma unroll
    for (int mm = 0; mm < 4; mm++) {
        const int row = 8 * h + 2 * mm;
        float lo, hi;
        unpack2(zst[mm], lo, hi);
        g_Zagg[ab + row * 16 + j] = lo;
        g_Zagg[ab + (row + 1) * 16 + j] = hi;
        unpack2(pst[mm], lo, hi);
        g_Pagg[ab + row * 16 + j] = lo;
        g_Pagg[ab + (row + 1) * 16 + j] = hi;
    }
}

// ============================================================================
// Phase 2: per-chain scan of NCHUNK aggregates, depth-8 cp.async pipeline.
// ============================================================================
#define P2D 8

__global__ void phase2_kernel()
{
    __shared__ __align__(16) float sP[P2D][256];
    __shared__ __align__(16) float sZ[P2D][256];

    const int chain = blockIdx.x;
    const int lane  = threadIdx.x;
    const int col   = lane & 15;
    const bool zside = (lane < 16);

    const float* Pbase = g_Pagg + (size_t)chain * NCHUNK * 256;
    const float* Zbase = g_Zagg + (size_t)chain * NCHUNK * 256;

#pragma unroll 1
    for (int d = 0; d < P2D - 1; d++) {
        cp16(sP[d] + lane * 8,     Pbase + d * 256 + lane * 8);
        cp16(sP[d] + lane * 8 + 4, Pbase + d * 256 + lane * 8 + 4);
        cp16(sZ[d] + lane * 8,     Zbase + d * 256 + lane * 8);
        cp16(sZ[d] + lane * 8 + 4, Zbase + d * 256 + lane * 8 + 4);
        CP_COMMIT();
    }

    u64 ypk[8];
#pragma unroll
    for (int m = 0; m < 8; m++) ypk[m] = 0ull;

#pragma unroll 1
    for (int cix = 0; cix < NCHUNK; cix++) {
        const int buf = cix & (P2D - 1);
        const int pre = cix + P2D - 1;
        if (pre < NCHUNK) {
            const int pb = pre & (P2D - 1);
            cp16(sP[pb] + lane * 8,     Pbase + pre * 256 + lane * 8);
            cp16(sP[pb] + lane * 8 + 4, Pbase + pre * 256 + lane * 8 + 4);
            cp16(sZ[pb] + lane * 8,     Zbase + pre * 256 + lane * 8);
            cp16(sZ[pb] + lane * 8 + 4, Zbase + pre * 256 + lane * 8 + 4);
        }
        CP_COMMIT();
        CP_WAIT7();
        __syncwarp();

        if (zside) {
            const int base = (chain * NCHUNK + cix) * 256;
            float cl[16];
#pragma unroll
            for (int m = 0; m < 8; m++) unpack2(ypk[m], cl[2 * m], cl[2 * m + 1]);
#pragma unroll
            for (int i = 0; i < 16; i++) g_carry[base + i * 16 + col] = cl[i];

            float yn[16];
#pragma unroll
            for (int i = 0; i < 16; i++) {
                const ulonglong2* pr = (const ulonglong2*)(sP[buf] + i * 16);
                ulonglong2 a0 = pr[0], a1 = pr[1], a2 = pr[2], a3 = pr[3];
                u64 acc0 = ffma2(a0.x, ypk[0], 0ull);
                u64 acc1 = ffma2(a2.x, ypk[4], 0ull);
                acc0 = ffma2(a0.y, ypk[1], acc0);
                acc1 = ffma2(a2.y, ypk[5], acc1);
                acc0 = ffma2(a1.x, ypk[2], acc0);
                acc1 = ffma2(a3.x, ypk[6], acc1);
                acc0 = ffma2(a1.y, ypk[3], acc0);
                acc1 = ffma2(a3.y, ypk[7], acc1);
                float lo, hi;
                unpack2(add2(acc0, acc1), lo, hi);
                yn[i] = lo + hi + sZ[buf][i * 16 + col];
            }
#pragma unroll
            for (int m = 0; m < 8; m++) ypk[m] = pack2(yn[2 * m], yn[2 * m + 1]);
        }
        __syncwarp();
    }
}

// ============================================================================
// Phase 3: final pass, split-k, DEPTH-6 cp.async ring. Y written directly
// from registers via streaming STG.32.
// ============================================================================
#define P3D 6

__global__ void __launch_bounds__(64) phase3_kernel(
    const float* __restrict__ A, const float* __restrict__ X,
    float* __restrict__ Y)
{
    __shared__ __align__(16) float sm[2][P3D][512];

    const int wid  = threadIdx.x >> 5;
    const int lane = threadIdx.x & 31;
    const int w    = blockIdx.x * 2 + wid;
    const int chain = w / NCHUNK;
    const int chunk = w % NCHUNK;
    const int b = chain >> 4;
    const int c = chain & 15;
    const int t0 = chunk * TT;
    const int j = lane & 15;
    const int h = lane >> 4;

    const int base0 = ((b * LL + t0) * CC + c) * 256;
    const float* src = (h == 0 ? A : X) + base0 + j * 4;
    const int soff = (h == 0 ? 0 : 256) + j * 4;

    // prologue: stage steps 0..P3D-2
#pragma unroll
    for (int d = 0; d < P3D - 1; d++) {
        float* dn = sm[wid][d] + soff;
        const float* s2 = src + d * STEP_STRIDE;
#pragma unroll
        for (int q = 0; q < 4; q++) cp16(dn + q * 64, s2 + q * 64);
        CP_COMMIT();
    }

    // init state from carry: rows [8h, 8h+8) of column j
    u64 zst[4];
    {
        const int cb = w * 256;
#pragma unroll
        for (int mm = 0; mm < 4; mm++) {
            const int row = 8 * h + 2 * mm;
            zst[mm] = pack2(g_carry[cb + row * 16 + j],
                            g_carry[cb + (row + 1) * 16 + j]);
        }
    }

    // per-lane output base: column j, starting row 8h
    float* outc = Y + base0 + (8 * h) * 16 + j;

#pragma unroll 1
    for (int t = 0; t < TT; t++) {
        if (t + P3D - 1 < TT) {
            const float* s2 = src + (t + P3D - 1) * STEP_STRIDE;
            float* dn = sm[wid][(t + P3D - 1) % P3D] + soff;
#pragma unroll
            for (int q = 0; q < 4; q++) cp16(dn + q * 64, s2 + q * 64);
        }
        CP_COMMIT();
        CP_WAIT5();
        __syncwarp();

        const float* As = sm[wid][t % P3D];
        const float* Xs = As + 256;
        const float* Ah = As + h * 8;

        float zpL[8], zpH[8];
#pragma unroll
        for (int r = 0; r < 8; r++) {
            ulonglong2 a0 = *(const ulonglong2*)(Ah + r * 16);
            ulonglong2 a1 = *(const ulonglong2*)(Ah + r * 16 + 4);
            zpL[r] = dot8(a0, a1, zst);
            ulonglong2 b0 = *(const ulonglong2*)(Ah + (8 + r) * 16);
            ulonglong2 b1 = *(const ulonglong2*)(Ah + (8 + r) * 16 + 4);
            zpH[r] = dot8(b0, b1, zst);
        }

        float zn[8];
#pragma unroll
        for (int r = 0; r < 8; r++) {
            float zsend = h ? zpL[r] : zpH[r];
            float zrecv = __shfl_xor_sync(0xffffffffu, zsend, 16);
            float zown  = h ? zpH[r] : zpL[r];
            float xv = Xs[(8 * h + r) * 16 + j];
            zn[r] = zown + zrecv + xv;
        }
#pragma unroll
        for (int mm = 0; mm < 4; mm++)
            zst[mm] = pack2(zn[2 * mm], zn[2 * mm + 1]);

        // direct streaming store of this lane's 8 Y elements
        float* out = outc + t * STEP_STRIDE;
#pragma unroll
        for (int r = 0; r < 8; r++) __stcs(out + r * 16, zn[r]);
    }
}

// ============================================================================
extern "C" void kernel_launch(void* const* d_in, const int* in_sizes, int n_in,
                              void* d_out, int out_size)
{
    const float* A = (const float*)d_in[0];
    const float* X = (const float*)d_in[1];
    float* Y = (float*)d_out;

    phase1_kernel<<<TOTCHUNK / 2, 64>>>(A, X);
    phase2_kernel<<<CHAINS, 32>>>();
    phase3_kernel<<<TOTCHUNK / 2, 64>>>(A, X, Y);
}

// round 11
// speedup vs baseline: 1.0028x; 1.0028x over previous
#include <cuda_runtime.h>
#include <cstdint>

// PScan: Y_t = A_t @ Y_{t-1} + X_t  (Y_0 = X_0), per (b,c) chain.
// Shapes: A,X,Y = [B=4, L=2048, C=16, 16, 16] fp32, row-major.
// Chunked scan (TT=32), cp.async staging, f32x2 FFMA, split-k half-warps.
// Phase3: depth-6 cp.async ring + direct streaming STG.32.

#define BB 4
#define LL 2048
#define CC 16
#define TT 32
#define NCHUNK (LL / TT)            // 64
#define CHAINS (BB * CC)            // 64
#define TOTCHUNK (CHAINS * NCHUNK)  // 4096
#define STEP_STRIDE (CC * 256)

typedef unsigned long long u64;

__device__ float g_Pagg[TOTCHUNK * 256];
__device__ float g_Zagg[TOTCHUNK * 256];
__device__ float g_carry[TOTCHUNK * 256];

__device__ __forceinline__ u64 ffma2(u64 a, u64 b, u64 c) {
    u64 d;
    asm("fma.rn.f32x2 %0, %1, %2, %3;" : "=l"(d) : "l"(a), "l"(b), "l"(c));
    return d;
}
__device__ __forceinline__ u64 add2(u64 a, u64 b) {
    u64 d;
    asm("add.rn.f32x2 %0, %1, %2;" : "=l"(d) : "l"(a), "l"(b));
    return d;
}
__device__ __forceinline__ u64 pack2(float lo, float hi) {
    u64 d;
    asm("mov.b64 %0, {%1, %2};" : "=l"(d) : "f"(lo), "f"(hi));
    return d;
}
__device__ __forceinline__ void unpack2(u64 v, float& lo, float& hi) {
    asm("mov.b64 {%0, %1}, %2;" : "=f"(lo), "=f"(hi) : "l"(v));
}

__device__ __forceinline__ void cp16(float* smem_dst, const float* gsrc) {
    uint32_t s = (uint32_t)__cvta_generic_to_shared(smem_dst);
    asm volatile("cp.async.ca.shared.global [%0], [%1], 16;\n" :: "r"(s), "l"(gsrc));
}
#define CP_COMMIT() asm volatile("cp.async.commit_group;\n" ::: "memory")
#define CP_WAIT0()  asm volatile("cp.async.wait_group 0;\n" ::: "memory")
#define CP_WAIT1()  asm volatile("cp.async.wait_group 1;\n" ::: "memory")
#define CP_WAIT5()  asm volatile("cp.async.wait_group 5;\n" ::: "memory")
#define CP_WAIT7()  asm volatile("cp.async.wait_group 7;\n" ::: "memory")

// partial dot of one A-row k-half (a0,a1 = 4 f32x2) with packed state st[4]
__device__ __forceinline__ float dot8(ulonglong2 a0, ulonglong2 a1, const u64* st)
{
    u64 acc0 = ffma2(a0.x, st[0], 0ull);
    u64 acc1 = ffma2(a0.y, st[1], 0ull);
    acc0 = ffma2(a1.x, st[2], acc0);
    acc1 = ffma2(a1.y, st[3], acc1);
    float lo, hi;
    unpack2(add2(acc0, acc1), lo, hi);
    return lo + hi;
}

// ============================================================================
// Phase 1 (R4/R7-proven): chunk aggregates, depth-2 double buffer, split-k.
// ============================================================================
__global__ void __launch_bounds__(64) phase1_kernel(
    const float* __restrict__ A, const float* __restrict__ X)
{
    __shared__ __align__(16) float sm[2][2][512];  // [warp][buf][A:256|X:256]

    const int wid  = threadIdx.x >> 5;
    const int lane = threadIdx.x & 31;
    const int w    = blockIdx.x * 2 + wid;
    const int chain = w / NCHUNK;
    const int chunk = w % NCHUNK;
    const int b = chain >> 4;
    const int c = chain & 15;
    const int t0 = chunk * TT;
    const int j = lane & 15;
    const int h = lane >> 4;

    const int base0 = ((b * LL + t0) * CC + c) * 256;
    const float* src = (h == 0 ? A : X) + base0 + j * 4;
    float* dst0 = sm[wid][0] + (h == 0 ? 0 : 256) + j * 4;
    float* dst1 = sm[wid][1] + (h == 0 ? 0 : 256) + j * 4;

#pragma unroll
    for (int q = 0; q < 4; q++) cp16(dst0 + q * 64, src + q * 64);
    CP_COMMIT();

    u64 zst[4], pst[4];
#pragma unroll
    for (int mm = 0; mm < 4; mm++) {
        zst[mm] = 0ull;
        int k0 = 8 * h + 2 * mm;
        pst[mm] = pack2(j == k0 ? 1.f : 0.f, j == k0 + 1 ? 1.f : 0.f);
    }

#pragma unroll 1
    for (int t = 0; t < TT; t++) {
        if (t + 1 < TT) {
            const float* s2 = src + (t + 1) * STEP_STRIDE;
            float* dn = (t & 1) ? dst0 : dst1;
#pragma unroll
            for (int q = 0; q < 4; q++) cp16(dn + q * 64, s2 + q * 64);
            CP_COMMIT();
            CP_WAIT1();
        } else {
            CP_WAIT0();
        }
        __syncwarp();

        const float* As = sm[wid][t & 1];
        const float* Xs = As + 256;
        const float* Ah = As + h * 8;

        float zpL[8], zpH[8], ppL[8], ppH[8];
#pragma unroll
        for (int r = 0; r < 8; r++) {
            ulonglong2 a0 = *(const ulonglong2*)(Ah + r * 16);
            ulonglong2 a1 = *(const ulonglong2*)(Ah + r * 16 + 4);
            zpL[r] = dot8(a0, a1, zst);
            ppL[r] = dot8(a0, a1, pst);
            ulonglong2 b0 = *(const ulonglong2*)(Ah + (8 + r) * 16);
            ulonglong2 b1 = *(const ulonglong2*)(Ah + (8 + r) * 16 + 4);
            zpH[r] = dot8(b0, b1, zst);
            ppH[r] = dot8(b0, b1, pst);
        }

        float zn[8], pn[8];
#pragma unroll
        for (int r = 0; r < 8; r++) {
            float zsend = h ? zpL[r] : zpH[r];
            float zrecv = __shfl_xor_sync(0xffffffffu, zsend, 16);
            float zown  = h ? zpH[r] : zpL[r];
            float xv = Xs[(8 * h + r) * 16 + j];
            zn[r] = zown + zrecv + xv;

            float psend = h ? ppL[r] : ppH[r];
            float precv = __shfl_xor_sync(0xffffffffu, psend, 16);
            float pown  = h ? ppH[r] : ppL[r];
            pn[r] = pown + precv;
        }
#pragma unroll
        for (int mm = 0; mm < 4; mm++) {
            zst[mm] = pack2(zn[2 * mm], zn[2 * mm + 1]);
            pst[mm] = pack2(pn[2 * mm], pn[2 * mm + 1]);
        }
        __syncwarp();
    }

    const int ab = w * 256;
#pragma unroll
    for (int mm = 0; mm < 4; mm++) {
        const int row = 8 * h + 2 * mm;
        float lo, hi;
        unpack2(zst[mm], lo, hi);
        g_Zagg[ab + row * 16 + j] = lo;
        g_Zagg[ab + (row + 1) * 16 + j] = hi;
        unpack2(pst[mm], lo, hi);
        g_Pagg[ab + row * 16 + j] = lo;
        g_Pagg[ab + (row + 1) * 16 + j] = hi;
    }
}

// ============================================================================
// Phase 2: per-chain scan of NCHUNK aggregates, depth-8 cp.async pipeline.
// ============================================================================
#define P2D 8

__global__ void phase2_kernel()
{
    __shared__ __align__(16) float sP[P2D][256];
    __shared__ __align__(16) float sZ[P2D][256];

    const int chain = blockIdx.x;
    const int lane  = threadIdx.x;
    const int col   = lane & 15;
    const bool zside = (lane < 16);

    const float* Pbase = g_Pagg + (size_t)chain * NCHUNK * 256;
    const float* Zbase = g_Zagg + (size_t)chain * NCHUNK * 256;

#pragma unroll 1
    for (int d = 0; d < P2D - 1; d++) {
        cp16(sP[d] + lane * 8,     Pbase + d * 256 + lane * 8);
        cp16(sP[d] + lane * 8 + 4, Pbase + d * 256 + lane * 8 + 4);
        cp16(sZ[d] + lane * 8,     Zbase + d * 256 + lane * 8);
        cp16(sZ[d] + lane * 8 + 4, Zbase + d * 256 + lane * 8 + 4);
        CP_COMMIT();
    }

    u64 ypk[8];
#pragma unroll
    for (int m = 0; m < 8; m++) ypk[m] = 0ull;

#pragma unroll 1
    for (int cix = 0; cix < NCHUNK; cix++) {
        const int buf = cix & (P2D - 1);
        const int pre = cix + P2D - 1;
        if (pre < NCHUNK) {
            const int pb = pre & (P2D - 1);
            cp16(sP[pb] + lane * 8,     Pbase + pre * 256 + lane * 8);
            cp16(sP[pb] + lane * 8 + 4, Pbase + pre * 256 + lane * 8 + 4);
            cp16(sZ[pb] + lane * 8,     Zbase + pre * 256 + lane * 8);
            cp16(sZ[pb] + lane * 8 + 4, Zbase + pre * 256 + lane * 8 + 4);
        }
        CP_COMMIT();
        CP_WAIT7();
        __syncwarp();

        if (zside) {
            const int base = (chain * NCHUNK + cix) * 256;
            float cl[16];
#pragma unroll
            for (int m = 0; m < 8; m++) unpack2(ypk[m], cl[2 * m], cl[2 * m + 1]);
#pragma unroll
            for (int i = 0; i < 16; i++) g_carry[base + i * 16 + col] = cl[i];

            float yn[16];
#pragma unroll
            for (int i = 0; i < 16; i++) {
                const ulonglong2* pr = (const ulonglong2*)(sP[buf] + i * 16);
                ulonglong2 a0 = pr[0], a1 = pr[1], a2 = pr[2], a3 = pr[3];
                u64 acc0 = ffma2(a0.x, ypk[0], 0ull);
                u64 acc1 = ffma2(a2.x, ypk[4], 0ull);
                acc0 = ffma2(a0.y, ypk[1], acc0);
                acc1 = ffma2(a2.y, ypk[5], acc1);
                acc0 = ffma2(a1.x, ypk[2], acc0);
                acc1 = ffma2(a3.x, ypk[6], acc1);
                acc0 = ffma2(a1.y, ypk[3], acc0);
                acc1 = ffma2(a3.y, ypk[7], acc1);
                float lo, hi;
                unpack2(add2(acc0, acc1), lo, hi);
                yn[i] = lo + hi + sZ[buf][i * 16 + col];
            }
#pragma unroll
            for (int m = 0; m < 8; m++) ypk[m] = pack2(yn[2 * m], yn[2 * m + 1]);
        }
        __syncwarp();
    }
}

// ============================================================================
// Phase 3: final pass, split-k, DEPTH-6 cp.async ring. Y written directly
// from registers via streaming STG.32.
// ============================================================================
#define P3D 6

__global__ void __launch_bounds__(64) phase3_kernel(
    const float* __restrict__ A, const float* __restrict__ X,
    float* __restrict__ Y)
{
    __shared__ __align__(16) float sm[2][P3D][512];

    const int wid  = threadIdx.x >> 5;
    const int lane = threadIdx.x & 31;
    const int w    = blockIdx.x * 2 + wid;
    const int chain = w / NCHUNK;
    const int chunk = w % NCHUNK;
    const int b = chain >> 4;
    const int c = chain & 15;
    const int t0 = chunk * TT;
    const int j = lane & 15;
    const int h = lane >> 4;

    const int base0 = ((b * LL + t0) * CC + c) * 256;
    const float* src = (h == 0 ? A : X) + base0 + j * 4;
    const int soff = (h == 0 ? 0 : 256) + j * 4;

    // prologue: stage steps 0..P3D-2
#pragma unroll
    for (int d = 0; d < P3D - 1; d++) {
        float* dn = sm[wid][d] + soff;
        const float* s2 = src + d * STEP_STRIDE;
#pragma unroll
        for (int q = 0; q < 4; q++) cp16(dn + q * 64, s2 + q * 64);
        CP_COMMIT();
    }

    // init state from carry: rows [8h, 8h+8) of column j
    u64 zst[4];
    {
        const int cb = w * 256;
#pragma unroll
        for (int mm = 0; mm < 4; mm++) {
            const int row = 8 * h + 2 * mm;
            zst[mm] = pack2(g_carry[cb + row * 16 + j],
                            g_carry[cb + (row + 1) * 16 + j]);
        }
    }

    // per-lane output base: column j, starting row 8h
    float* outc = Y + base0 + (8 * h) * 16 + j;

#pragma unroll 1
    for (int t = 0; t < TT; t++) {
        if (t + P3D - 1 < TT) {
            const float* s2 = src + (t + P3D - 1) * STEP_STRIDE;
            float* dn = sm[wid][(t + P3D - 1) % P3D] + soff;
#pragma unroll
            for (int q = 0; q < 4; q++) cp16(dn + q * 64, s2 + q * 64);
        }
        CP_COMMIT();
        CP_WAIT5();
        __syncwarp();

        const float* As = sm[wid][t % P3D];
        const float* Xs = As + 256;
        const float* Ah = As + h * 8;

        float zpL[8], zpH[8];
#pragma unroll
        for (int r = 0; r < 8; r++) {
            ulonglong2 a0 = *(const ulonglong2*)(Ah + r * 16);
            ulonglong2 a1 = *(const ulonglong2*)(Ah + r * 16 + 4);
            zpL[r] = dot8(a0, a1, zst);
            ulonglong2 b0 = *(const ulonglong2*)(Ah + (8 + r) * 16);
            ulonglong2 b1 = *(const ulonglong2*)(Ah + (8 + r) * 16 + 4);
            zpH[r] = dot8(b0, b1, zst);
        }

        float zn[8];
#pragma unroll
        for (int r = 0; r < 8; r++) {
            float zsend = h ? zpL[r] : zpH[r];
            float zrecv = __shfl_xor_sync(0xffffffffu, zsend, 16);
            float zown  = h ? zpH[r] : zpL[r];
            float xv = Xs[(8 * h + r) * 16 + j];
            zn[r] = zown + zrecv + xv;
        }
#pragma unroll
        for (int mm = 0; mm < 4; mm++)
            zst[mm] = pack2(zn[2 * mm], zn[2 * mm + 1]);

        // direct streaming store of this lane's 8 Y elements
        float* out = outc + t * STEP_STRIDE;
#pragma unroll
        for (int r = 0; r < 8; r++) __stcs(out + r * 16, zn[r]);
    }
}

// ============================================================================
extern "C" void kernel_launch(void* const* d_in, const int* in_sizes, int n_in,
                              void* d_out, int out_size)
{
    const float* A = (const float*)d_in[0];
    const float* X = (const float*)d_in[1];
    float* Y = (float*)d_out;

    phase1_kernel<<<TOTCHUNK / 2, 64>>>(A, X);
    phase2_kernel<<<CHAINS, 32>>>();
    phase3_kernel<<<TOTCHUNK / 2, 64>>>(A, X, Y);
}